// round 11
// baseline (speedup 1.0000x reference)
#include <cuda_runtime.h>
#include <cuda_bf16.h>
#include <stdint.h>

// Problem constants (fixed shapes)
#define B_ROWS 2048
#define RSZ    10
#define DIM    1024
#define NTGT   (B_ROWS * (RSZ - 1))   // 18432 targets
#define INV_TEMP 20.0f
#define ALPHA_C  1.0f
#define BETA_C   0.5f

// ---------------- device scratch ----------------
__device__ uint32_t g_qa[(size_t)B_ROWS * (DIM / 4)];  // int8 anchors (packed x4)
__device__ uint32_t g_qt[(size_t)NTGT * (DIM / 4)];    // int8 targets (packed x4)
__device__ float g_sa[B_ROWS];   // anchor dequant scale
__device__ float g_st[NTGT];     // target dequant scale
__device__ float g_diag[B_ROWS];
__device__ float g_kl[B_ROWS];
__device__ float g_Z[B_ROWS];
__device__ unsigned int g_count; // zero at load; last CTA resets each launch

__device__ __forceinline__ float warpReduceSum(float v) {
    v += __shfl_xor_sync(0xffffffffu, v, 16);
    v += __shfl_xor_sync(0xffffffffu, v, 8);
    v += __shfl_xor_sync(0xffffffffu, v, 4);
    v += __shfl_xor_sync(0xffffffffu, v, 2);
    v += __shfl_xor_sync(0xffffffffu, v, 1);
    return v;
}
__device__ __forceinline__ float warpReduceMax(float v) {
    v = fmaxf(v, __shfl_xor_sync(0xffffffffu, v, 16));
    v = fmaxf(v, __shfl_xor_sync(0xffffffffu, v, 8));
    v = fmaxf(v, __shfl_xor_sync(0xffffffffu, v, 4));
    v = fmaxf(v, __shfl_xor_sync(0xffffffffu, v, 2));
    v = fmaxf(v, __shfl_xor_sync(0xffffffffu, v, 1));
    return v;
}

// pack 4 rounded int32 -> 4 saturated s8 bytes (x0 in byte0 .. x3 in byte3)
__device__ __forceinline__ uint32_t pack_s8x4(int x0, int x1, int x2, int x3) {
    uint32_t hi, r;
    asm("cvt.pack.sat.s8.s32.b32 %0, %1, %2, %3;" : "=r"(hi) : "r"(x3), "r"(x2), "r"(0));
    asm("cvt.pack.sat.s8.s32.b32 %0, %1, %2, %3;" : "=r"(r)  : "r"(x1), "r"(x0), "r"(hi));
    return r;
}

// ---------------------------------------------------------------------------
// Kernel 1: two-pass streaming prep; cvt.pack quantize; 4 blocks/SM.
// (FROZEN from R10 — 20.9 us, no spill, alu-thin)
// ---------------------------------------------------------------------------
__global__ void __launch_bounds__(320, 4) prep_kernel(const float* __restrict__ emb,
                                                      const float* __restrict__ scores) {
    const int b    = blockIdx.x;
    const int tid  = threadIdx.x;
    const int lane = tid & 31;
    const int warp = tid >> 5;        // 0..9 = row index

    __shared__ float4 s_a4[DIM / 4];  // raw anchor (4 KB)
    __shared__ float  s_cos[RSZ];
    __shared__ float  s_inv0;

    const float4* row4 = reinterpret_cast<const float4*>(emb)
                       + ((size_t)b * RSZ + warp) * (DIM / 4);

    // ---- pass 1: sum of squares + maxabs ----
    float ss = 0.f, mm = 0.f;
#pragma unroll
    for (int i = 0; i < 8; ++i) {
        float4 t = row4[lane + 32 * i];
        ss += t.x * t.x + t.y * t.y + t.z * t.z + t.w * t.w;
        mm = fmaxf(mm, fmaxf(fmaxf(fabsf(t.x), fabsf(t.y)),
                             fmaxf(fabsf(t.z), fabsf(t.w))));
        if (warp == 0) s_a4[lane + 32 * i] = t;   // park raw anchor in smem
    }
    ss = warpReduceSum(ss);
    mm = warpReduceMax(mm);

    const float inv  = 1.0f / fmaxf(sqrtf(ss), 1e-12f);
    const float maxn = fmaxf(mm * inv, 1e-20f);
    const float qs   = inv * (127.0f / maxn);
    const float dq   = maxn * (1.0f / 127.0f);

    if (lane == 0) {
        if      (warp == 0) { g_sa[b] = dq; s_inv0 = inv; }
        else if (warp == 1) g_st[b] = dq;
        else                g_st[B_ROWS + (size_t)b * 8 + (warp - 2)] = dq;
    }
    __syncthreads();
    const float inv0 = s_inv0;

    // ---- pass 2: re-read row (L2-hit), dot vs raw anchor, quantize+store ----
    uint32_t* drow;
    if      (warp == 0) drow = g_qa + (size_t)b * 256;
    else if (warp == 1) drow = g_qt + (size_t)b * 256;
    else                drow = g_qt + ((size_t)B_ROWS + (size_t)b * 8 + (warp - 2)) * 256;

    float d = 0.f;
#pragma unroll
    for (int i = 0; i < 8; ++i) {
        float4 t = row4[lane + 32 * i];
        float4 a = s_a4[lane + 32 * i];
        d += t.x * a.x + t.y * a.y + t.z * a.z + t.w * a.w;
        drow[lane + 32 * i] = pack_s8x4(__float2int_rn(t.x * qs),
                                        __float2int_rn(t.y * qs),
                                        __float2int_rn(t.z * qs),
                                        __float2int_rn(t.w * qs));
    }
    d = warpReduceSum(d);
    if (lane == 0) s_cos[warp] = d * inv * inv0;   // cos(anchor, row_warp)
    __syncthreads();

    if (tid == 0) {
        float rs[9], sc[9];
#pragma unroll
        for (int k = 0; k < 9; ++k) { rs[k] = s_cos[k + 1]; sc[k] = scores[(size_t)b * 9 + k]; }
        float m1 = sc[0], m2 = rs[0];
#pragma unroll
        for (int k = 1; k < 9; ++k) { m1 = fmaxf(m1, sc[k]); m2 = fmaxf(m2, rs[k]); }
        float z1 = 0.f, z2 = 0.f;
#pragma unroll
        for (int k = 0; k < 9; ++k) { z1 += expf(sc[k] - m1); z2 += expf(rs[k] - m2); }
        const float lz1 = logf(z1), lz2 = logf(z2);
        float kl = 0.f;
#pragma unroll
        for (int k = 0; k < 9; ++k) {
            float lce = sc[k] - m1 - lz1;
            float ce  = expf(lce);
            float lp  = rs[k] - m2 - lz2;
            kl += ce * (lce - lp);
        }
        g_kl[b]   = kl / (float)(RSZ - 1);
        g_diag[b] = rs[0] * INV_TEMP;
        g_Z[b]    = 0.0f;
    }
}

// ---------------------------------------------------------------------------
// Kernel 2: int8 IMMA GEMM + dequant + exp row-sum + LAST-CTA finalize.
// 128x128 CTA tile, warp tile 64x32 (2x4 warps), K=64/stage, 4-stage, 2 CTA/SM.
// ---------------------------------------------------------------------------
#define TILE_M  128
#define TILE_N  128
#define STAGES  4
#define NUM_KT  16                       // 1024 / 64
#define A_STG   (TILE_M * 80)            // 10240 B
#define B_STG   (TILE_N * 80)            // 10240 B
#define STG_B   (A_STG + B_STG)          // 20480 B
#define GEMM_SMEM_TOTAL (STAGES * STG_B) // 81920 B -> 2 CTAs/SM
#define GRID_TOTAL ((NTGT / TILE_N) * (B_ROWS / TILE_M))   // 2304 CTAs

__device__ __forceinline__ void ldsm_x4(uint32_t addr, uint32_t* r) {
    asm volatile("ldmatrix.sync.aligned.m8n8.x4.shared.b16 {%0,%1,%2,%3}, [%4];"
                 : "=r"(r[0]), "=r"(r[1]), "=r"(r[2]), "=r"(r[3])
                 : "r"(addr));
}
__device__ __forceinline__ void mma_s8(int* d, const uint32_t* a, uint32_t b0, uint32_t b1) {
    asm volatile(
        "mma.sync.aligned.m16n8k32.row.col.s32.s8.s8.s32 "
        "{%0,%1,%2,%3}, {%4,%5,%6,%7}, {%8,%9}, {%0,%1,%2,%3};"
        : "+r"(d[0]), "+r"(d[1]), "+r"(d[2]), "+r"(d[3])
        : "r"(a[0]), "r"(a[1]), "r"(a[2]), "r"(a[3]), "r"(b0), "r"(b1));
}
__device__ __forceinline__ void cp_async_16(uint32_t dst, const void* src) {
    asm volatile("cp.async.cg.shared.global [%0], [%1], 16;" :: "r"(dst), "l"(src));
}

__global__ void __launch_bounds__(256, 2) gemm_z_kernel(float* __restrict__ out) {
    extern __shared__ char smem[];
    const uint32_t sb = (uint32_t)__cvta_generic_to_shared(smem);

    const int bn   = blockIdx.x;     // 0..143 (128 targets)
    const int bm   = blockIdx.y;     // 0..15  (128 anchors)
    const int tid  = threadIdx.x;
    const int lane = tid & 31;
    const int warp = tid >> 5;
    const int wm   = warp & 1;       // 2 warps along M (64 rows)
    const int wn   = warp >> 1;      // 4 warps along N (32 cols)

    int acc[4][4][4];                // 64 regs
#pragma unroll
    for (int i = 0; i < 4; ++i)
#pragma unroll
        for (int j = 0; j < 4; ++j)
#pragma unroll
            for (int c = 0; c < 4; ++c) acc[i][j][c] = 0;

    const int lrow = tid >> 2;       // 0..63
    const int c    = tid & 3;        // 16B chunk of 64B K-slice
    const char* gA = (const char*)g_qa + ((size_t)(bm * TILE_M + lrow)) * 1024 + c * 16;
    const char* gB = (const char*)g_qt + ((size_t)(bn * TILE_N + lrow)) * 1024 + c * 16;
    const uint32_t sA0 = sb + lrow * 80 + c * 16;
    const uint32_t sB0 = sb + A_STG + lrow * 80 + c * 16;

    auto issue_loads = [&](int slot, int kt) {
        const size_t ko = (size_t)kt * 64;
        const uint32_t so = slot * STG_B;
#pragma unroll
        for (int p = 0; p < 2; ++p)
            cp_async_16(sA0 + so + p * (64 * 80), gA + ko + (size_t)p * (64 * 1024));
#pragma unroll
        for (int p = 0; p < 2; ++p)
            cp_async_16(sB0 + so + p * (64 * 80), gB + ko + (size_t)p * (64 * 1024));
        asm volatile("cp.async.commit_group;");
    };

#pragma unroll
    for (int s = 0; s < STAGES - 1; ++s) issue_loads(s, s);

    const uint32_t aRowBase = (uint32_t)(wm * 64 + (lane & 15));
    const uint32_t bRowBase = (uint32_t)(wn * 32 + (lane & 15));
    const uint32_t halfoff  = ((uint32_t)(lane >> 4)) << 4;

    for (int it = 0; it < NUM_KT; ++it) {
        const int slot = it & (STAGES - 1);

        if (it < NUM_KT - 2)       asm volatile("cp.async.wait_group 2;" ::: "memory");
        else if (it == NUM_KT - 2) asm volatile("cp.async.wait_group 1;" ::: "memory");
        else                       asm volatile("cp.async.wait_group 0;" ::: "memory");
        __syncthreads();

        if (it + STAGES - 1 < NUM_KT)
            issue_loads((it + STAGES - 1) & (STAGES - 1), it + STAGES - 1);

        const uint32_t saStage = sb + slot * STG_B;
        const uint32_t sbStage = saStage + A_STG;

#pragma unroll
        for (int kk = 0; kk < 2; ++kk) {
            const uint32_t byteoff = halfoff + kk * 32;
            uint32_t af[4][4], bf[2][4];
#pragma unroll
            for (int mi = 0; mi < 4; ++mi)
                ldsm_x4(saStage + (aRowBase + mi * 16) * 80u + byteoff, af[mi]);
#pragma unroll
            for (int nt = 0; nt < 2; ++nt)
                ldsm_x4(sbStage + (bRowBase + nt * 16) * 80u + byteoff, bf[nt]);
#pragma unroll
            for (int mi = 0; mi < 4; ++mi)
#pragma unroll
                for (int nt = 0; nt < 2; ++nt) {
                    mma_s8(acc[mi][nt * 2 + 0], af[mi], bf[nt][0], bf[nt][2]);
                    mma_s8(acc[mi][nt * 2 + 1], af[mi], bf[nt][1], bf[nt][3]);
                }
        }
    }
    __syncthreads();   // stages dead; reuse smem

    // ---- epilogue: dequant, exp, row-reduce ----
    float* sSa = (float*)smem;               // [0,128)
    float* sSt = (float*)smem + 128;         // [128,256)
    float* sZ  = (float*)smem + 256;         // [256,384)
    if (tid < 128) {
        sSa[tid] = g_sa[bm * TILE_M + tid];
        sSt[tid] = g_st[bn * TILE_N + tid];
        sZ[tid]  = 0.f;
    }
    __syncthreads();

#pragma unroll
    for (int mi = 0; mi < 4; ++mi) {
        const int row0 = wm * 64 + mi * 16 + (lane >> 2);
        const float a0 = sSa[row0]     * INV_TEMP;
        const float a1 = sSa[row0 + 8] * INV_TEMP;
        float s0 = 0.f, s1 = 0.f;
#pragma unroll
        for (int ni = 0; ni < 4; ++ni) {
            const int col = wn * 32 + ni * 8 + 2 * (lane & 3);
            const float b0 = sSt[col], b1 = sSt[col + 1];
            s0 += __expf((float)acc[mi][ni][0] * a0 * b0)
                + __expf((float)acc[mi][ni][1] * a0 * b1);
            s1 += __expf((float)acc[mi][ni][2] * a1 * b0)
                + __expf((float)acc[mi][ni][3] * a1 * b1);
        }
        s0 += __shfl_xor_sync(0xffffffffu, s0, 1);
        s0 += __shfl_xor_sync(0xffffffffu, s0, 2);
        s1 += __shfl_xor_sync(0xffffffffu, s1, 1);
        s1 += __shfl_xor_sync(0xffffffffu, s1, 2);
        if ((lane & 3) == 0) {
            const int rl = wm * 64 + mi * 16 + (lane >> 2);
            atomicAdd(&sZ[rl],     s0);
            atomicAdd(&sZ[rl + 8], s1);
        }
    }
    __syncthreads();
    if (tid < TILE_M) atomicAdd(&g_Z[bm * TILE_M + tid], sZ[tid]);

    // ---- last-CTA finalize (replaces the finalize kernel launch) ----
    __threadfence();
    __shared__ unsigned int s_last;
    if (tid == 0) {
        unsigned int t = atomicAdd(&g_count, 1u);
        s_last = (t == GRID_TOTAL - 1) ? 1u : 0u;
    }
    __syncthreads();
    if (s_last) {
        float* skl = (float*)smem;           // reuse smem
        float* sce = (float*)smem + 8;
        float akl = 0.f, ace = 0.f;
        for (int b = tid; b < B_ROWS; b += 256) {
            akl += g_kl[b];
            ace += logf(__ldcg(&g_Z[b])) - g_diag[b];
        }
        akl = warpReduceSum(akl);
        ace = warpReduceSum(ace);
        if (lane == 0) { skl[warp] = akl; sce[warp] = ace; }
        __syncthreads();
        if (tid == 0) {
            float k = 0.f, c2 = 0.f;
#pragma unroll
            for (int w = 0; w < 8; ++w) { k += skl[w]; c2 += sce[w]; }
            out[0] = BETA_C * (k / (float)B_ROWS) + ALPHA_C * (c2 / (float)B_ROWS);
            g_count = 0;                      // reset for next graph replay
        }
    }
}

// ---------------------------------------------------------------------------
extern "C" void kernel_launch(void* const* d_in, const int* in_sizes, int n_in,
                              void* d_out, int out_size) {
    const float* emb    = (const float*)d_in[0];
    const float* scores = (const float*)d_in[1];

    cudaFuncSetAttribute(gemm_z_kernel,
                         cudaFuncAttributeMaxDynamicSharedMemorySize, GEMM_SMEM_TOTAL);

    prep_kernel<<<B_ROWS, 320>>>(emb, scores);
    dim3 grid(NTGT / TILE_N, B_ROWS / TILE_M);   // (144, 16)
    gemm_z_kernel<<<grid, 256, GEMM_SMEM_TOTAL>>>((float*)d_out);
}

// round 12
// speedup vs baseline: 1.0856x; 1.0856x over previous
#include <cuda_runtime.h>
#include <cuda_bf16.h>
#include <stdint.h>

// Problem constants (fixed shapes)
#define B_ROWS 2048
#define RSZ    10
#define DIM    1024
#define NTGT   (B_ROWS * (RSZ - 1))   // 18432 targets
#define INV_TEMP 20.0f
#define ALPHA_C  1.0f
#define BETA_C   0.5f

// ---------------- device scratch ----------------
__device__ uint32_t g_qa[(size_t)B_ROWS * (DIM / 4)];  // int8 anchors (packed x4)
__device__ uint32_t g_qt[(size_t)NTGT * (DIM / 4)];    // int8 targets (packed x4)
__device__ float g_sa[B_ROWS];   // anchor dequant scale
__device__ float g_st[NTGT];     // target dequant scale
__device__ float g_diag[B_ROWS];
__device__ float g_kl[B_ROWS];
__device__ float g_Z[B_ROWS];

__device__ __forceinline__ float warpReduceSum(float v) {
    v += __shfl_xor_sync(0xffffffffu, v, 16);
    v += __shfl_xor_sync(0xffffffffu, v, 8);
    v += __shfl_xor_sync(0xffffffffu, v, 4);
    v += __shfl_xor_sync(0xffffffffu, v, 2);
    v += __shfl_xor_sync(0xffffffffu, v, 1);
    return v;
}
__device__ __forceinline__ float warpReduceMax(float v) {
    v = fmaxf(v, __shfl_xor_sync(0xffffffffu, v, 16));
    v = fmaxf(v, __shfl_xor_sync(0xffffffffu, v, 8));
    v = fmaxf(v, __shfl_xor_sync(0xffffffffu, v, 4));
    v = fmaxf(v, __shfl_xor_sync(0xffffffffu, v, 2));
    v = fmaxf(v, __shfl_xor_sync(0xffffffffu, v, 1));
    return v;
}

// pack 4 rounded int32 -> 4 saturated s8 bytes (x0 in byte0 .. x3 in byte3)
__device__ __forceinline__ uint32_t pack_s8x4(int x0, int x1, int x2, int x3) {
    uint32_t hi, r;
    asm("cvt.pack.sat.s8.s32.b32 %0, %1, %2, %3;" : "=r"(hi) : "r"(x3), "r"(x2), "r"(0));
    asm("cvt.pack.sat.s8.s32.b32 %0, %1, %2, %3;" : "=r"(r)  : "r"(x1), "r"(x0), "r"(hi));
    return r;
}

// ---------------------------------------------------------------------------
// Kernel 1: two-pass streaming prep; cvt.pack quantize; 4 blocks/SM.
// (FROZEN from R10 — 20.9 us)
// ---------------------------------------------------------------------------
__global__ void __launch_bounds__(320, 4) prep_kernel(const float* __restrict__ emb,
                                                      const float* __restrict__ scores) {
    const int b    = blockIdx.x;
    const int tid  = threadIdx.x;
    const int lane = tid & 31;
    const int warp = tid >> 5;        // 0..9 = row index

    __shared__ float4 s_a4[DIM / 4];  // raw anchor (4 KB)
    __shared__ float  s_cos[RSZ];
    __shared__ float  s_inv0;

    const float4* row4 = reinterpret_cast<const float4*>(emb)
                       + ((size_t)b * RSZ + warp) * (DIM / 4);

    // ---- pass 1: sum of squares + maxabs ----
    float ss = 0.f, mm = 0.f;
#pragma unroll
    for (int i = 0; i < 8; ++i) {
        float4 t = row4[lane + 32 * i];
        ss += t.x * t.x + t.y * t.y + t.z * t.z + t.w * t.w;
        mm = fmaxf(mm, fmaxf(fmaxf(fabsf(t.x), fabsf(t.y)),
                             fmaxf(fabsf(t.z), fabsf(t.w))));
        if (warp == 0) s_a4[lane + 32 * i] = t;   // park raw anchor in smem
    }
    ss = warpReduceSum(ss);
    mm = warpReduceMax(mm);

    const float inv  = 1.0f / fmaxf(sqrtf(ss), 1e-12f);
    const float maxn = fmaxf(mm * inv, 1e-20f);
    const float qs   = inv * (127.0f / maxn);
    const float dq   = maxn * (1.0f / 127.0f);

    if (lane == 0) {
        if      (warp == 0) { g_sa[b] = dq; s_inv0 = inv; }
        else if (warp == 1) g_st[b] = dq;
        else                g_st[B_ROWS + (size_t)b * 8 + (warp - 2)] = dq;
    }
    __syncthreads();
    const float inv0 = s_inv0;

    // ---- pass 2: re-read row (L2-hit), dot vs raw anchor, quantize+store ----
    uint32_t* drow;
    if      (warp == 0) drow = g_qa + (size_t)b * 256;
    else if (warp == 1) drow = g_qt + (size_t)b * 256;
    else                drow = g_qt + ((size_t)B_ROWS + (size_t)b * 8 + (warp - 2)) * 256;

    float d = 0.f;
#pragma unroll
    for (int i = 0; i < 8; ++i) {
        float4 t = row4[lane + 32 * i];
        float4 a = s_a4[lane + 32 * i];
        d += t.x * a.x + t.y * a.y + t.z * a.z + t.w * a.w;
        drow[lane + 32 * i] = pack_s8x4(__float2int_rn(t.x * qs),
                                        __float2int_rn(t.y * qs),
                                        __float2int_rn(t.z * qs),
                                        __float2int_rn(t.w * qs));
    }
    d = warpReduceSum(d);
    if (lane == 0) s_cos[warp] = d * inv * inv0;   // cos(anchor, row_warp)
    __syncthreads();

    if (tid == 0) {
        float rs[9], sc[9];
#pragma unroll
        for (int k = 0; k < 9; ++k) { rs[k] = s_cos[k + 1]; sc[k] = scores[(size_t)b * 9 + k]; }
        float m1 = sc[0], m2 = rs[0];
#pragma unroll
        for (int k = 1; k < 9; ++k) { m1 = fmaxf(m1, sc[k]); m2 = fmaxf(m2, rs[k]); }
        float z1 = 0.f, z2 = 0.f;
#pragma unroll
        for (int k = 0; k < 9; ++k) { z1 += expf(sc[k] - m1); z2 += expf(rs[k] - m2); }
        const float lz1 = logf(z1), lz2 = logf(z2);
        float kl = 0.f;
#pragma unroll
        for (int k = 0; k < 9; ++k) {
            float lce = sc[k] - m1 - lz1;
            float ce  = expf(lce);
            float lp  = rs[k] - m2 - lz2;
            kl += ce * (lce - lp);
        }
        g_kl[b]   = kl / (float)(RSZ - 1);
        g_diag[b] = rs[0] * INV_TEMP;
        g_Z[b]    = 0.0f;
    }
}

// ---------------------------------------------------------------------------
// Kernel 2: int8 IMMA GEMM + dequant + exp row-sum.
// NEW geometry: 64x128 CTA tile, warp tile 32x32 (2x4 warps), acc=32 regs,
// K=64/stage, 4-stage cp.async, 3 CTAs/SM (24 warps resident, +50% vs R10).
// ---------------------------------------------------------------------------
#define TILE_M  64
#define TILE_N  128
#define STAGES  4
#define NUM_KT  16                       // 1024 / 64
#define A_STG   (TILE_M * 80)            // 5120 B
#define B_STG   (TILE_N * 80)            // 10240 B
#define STG_B   (A_STG + B_STG)          // 15360 B
#define GEMM_SMEM_TOTAL (STAGES * STG_B) // 61440 B -> 3 CTAs/SM (184 KB)

__device__ __forceinline__ void ldsm_x4(uint32_t addr, uint32_t* r) {
    asm volatile("ldmatrix.sync.aligned.m8n8.x4.shared.b16 {%0,%1,%2,%3}, [%4];"
                 : "=r"(r[0]), "=r"(r[1]), "=r"(r[2]), "=r"(r[3])
                 : "r"(addr));
}
__device__ __forceinline__ void mma_s8(int* d, const uint32_t* a, uint32_t b0, uint32_t b1) {
    asm volatile(
        "mma.sync.aligned.m16n8k32.row.col.s32.s8.s8.s32 "
        "{%0,%1,%2,%3}, {%4,%5,%6,%7}, {%8,%9}, {%0,%1,%2,%3};"
        : "+r"(d[0]), "+r"(d[1]), "+r"(d[2]), "+r"(d[3])
        : "r"(a[0]), "r"(a[1]), "r"(a[2]), "r"(a[3]), "r"(b0), "r"(b1));
}
__device__ __forceinline__ void cp_async_16(uint32_t dst, const void* src) {
    asm volatile("cp.async.cg.shared.global [%0], [%1], 16;" :: "r"(dst), "l"(src));
}

__global__ void __launch_bounds__(256, 3) gemm_z_kernel() {
    extern __shared__ char smem[];
    const uint32_t sb = (uint32_t)__cvta_generic_to_shared(smem);

    const int bn   = blockIdx.x;     // 0..143 (128 targets)
    const int bm   = blockIdx.y;     // 0..31  (64 anchors)
    const int tid  = threadIdx.x;
    const int lane = tid & 31;
    const int warp = tid >> 5;
    const int wm   = warp & 1;       // 2 warps along M (32 rows)
    const int wn   = warp >> 1;      // 4 warps along N (32 cols)

    int acc[2][4][4];                // 32 regs
#pragma unroll
    for (int i = 0; i < 2; ++i)
#pragma unroll
        for (int j = 0; j < 4; ++j)
#pragma unroll
            for (int c = 0; c < 4; ++c) acc[i][j][c] = 0;

    const int lrow = tid >> 2;       // 0..63
    const int c    = tid & 3;        // 16B chunk of 64B K-slice
    const char* gA = (const char*)g_qa + ((size_t)(bm * TILE_M + lrow)) * 1024 + c * 16;
    const char* gB = (const char*)g_qt + ((size_t)(bn * TILE_N + lrow)) * 1024 + c * 16;
    const uint32_t sA0 = sb + lrow * 80 + c * 16;
    const uint32_t sB0 = sb + A_STG + lrow * 80 + c * 16;

    auto issue_loads = [&](int slot, int kt) {
        const size_t ko = (size_t)kt * 64;
        const uint32_t so = slot * STG_B;
        cp_async_16(sA0 + so, gA + ko);                                // 64 A rows
#pragma unroll
        for (int p = 0; p < 2; ++p)                                    // 128 B rows
            cp_async_16(sB0 + so + p * (64 * 80), gB + ko + (size_t)p * (64 * 1024));
        asm volatile("cp.async.commit_group;");
    };

#pragma unroll
    for (int s = 0; s < STAGES - 1; ++s) issue_loads(s, s);

    const uint32_t aRowBase = (uint32_t)(wm * 32 + (lane & 15));
    const uint32_t bRowBase = (uint32_t)(wn * 32 + (lane & 15));
    const uint32_t halfoff  = ((uint32_t)(lane >> 4)) << 4;

    for (int it = 0; it < NUM_KT; ++it) {
        const int slot = it & (STAGES - 1);

        if (it < NUM_KT - 2)       asm volatile("cp.async.wait_group 2;" ::: "memory");
        else if (it == NUM_KT - 2) asm volatile("cp.async.wait_group 1;" ::: "memory");
        else                       asm volatile("cp.async.wait_group 0;" ::: "memory");
        __syncthreads();

        if (it + STAGES - 1 < NUM_KT)
            issue_loads((it + STAGES - 1) & (STAGES - 1), it + STAGES - 1);

        const uint32_t saStage = sb + slot * STG_B;
        const uint32_t sbStage = saStage + A_STG;

#pragma unroll
        for (int kk = 0; kk < 2; ++kk) {
            const uint32_t byteoff = halfoff + kk * 32;
            uint32_t af[2][4], bf[2][4];
#pragma unroll
            for (int mi = 0; mi < 2; ++mi)
                ldsm_x4(saStage + (aRowBase + mi * 16) * 80u + byteoff, af[mi]);
#pragma unroll
            for (int nt = 0; nt < 2; ++nt)
                ldsm_x4(sbStage + (bRowBase + nt * 16) * 80u + byteoff, bf[nt]);
#pragma unroll
            for (int mi = 0; mi < 2; ++mi)
#pragma unroll
                for (int nt = 0; nt < 2; ++nt) {
                    mma_s8(acc[mi][nt * 2 + 0], af[mi], bf[nt][0], bf[nt][2]);
                    mma_s8(acc[mi][nt * 2 + 1], af[mi], bf[nt][1], bf[nt][3]);
                }
        }
    }
    __syncthreads();   // stages dead; reuse smem

    // ---- epilogue: dequant, exp, row-reduce ----
    float* sSa = (float*)smem;               // [0,64)
    float* sSt = (float*)smem + 64;          // [64,192)
    float* sZ  = (float*)smem + 192;         // [192,256)
    if (tid < 64) { sSa[tid] = g_sa[bm * TILE_M + tid]; sZ[tid] = 0.f; }
    if (tid < 128)  sSt[tid] = g_st[bn * TILE_N + tid];
    __syncthreads();

#pragma unroll
    for (int mi = 0; mi < 2; ++mi) {
        const int row0 = wm * 32 + mi * 16 + (lane >> 2);
        const float a0 = sSa[row0]     * INV_TEMP;
        const float a1 = sSa[row0 + 8] * INV_TEMP;
        float s0 = 0.f, s1 = 0.f;
#pragma unroll
        for (int ni = 0; ni < 4; ++ni) {
            const int col = wn * 32 + ni * 8 + 2 * (lane & 3);
            const float b0 = sSt[col], b1 = sSt[col + 1];
            s0 += __expf((float)acc[mi][ni][0] * a0 * b0)
                + __expf((float)acc[mi][ni][1] * a0 * b1);
            s1 += __expf((float)acc[mi][ni][2] * a1 * b0)
                + __expf((float)acc[mi][ni][3] * a1 * b1);
        }
        s0 += __shfl_xor_sync(0xffffffffu, s0, 1);
        s0 += __shfl_xor_sync(0xffffffffu, s0, 2);
        s1 += __shfl_xor_sync(0xffffffffu, s1, 1);
        s1 += __shfl_xor_sync(0xffffffffu, s1, 2);
        if ((lane & 3) == 0) {
            const int rl = wm * 32 + mi * 16 + (lane >> 2);
            atomicAdd(&sZ[rl],     s0);
            atomicAdd(&sZ[rl + 8], s1);
        }
    }
    __syncthreads();
    if (tid < TILE_M) atomicAdd(&g_Z[bm * TILE_M + tid], sZ[tid]);
}

// ---------------------------------------------------------------------------
// Kernel 3: final scalar reduction (restored — R11 fold-in regressed)
// ---------------------------------------------------------------------------
__global__ void __launch_bounds__(256) finalize_kernel(float* __restrict__ out) {
    const int tid  = threadIdx.x;
    const int lane = tid & 31;
    const int warp = tid >> 5;
    __shared__ float skl[8], sce[8];

    float akl = 0.f, ace = 0.f;
    for (int b = tid; b < B_ROWS; b += 256) {
        akl += g_kl[b];
        ace += logf(g_Z[b]) - g_diag[b];
    }
    akl = warpReduceSum(akl);
    ace = warpReduceSum(ace);
    if (lane == 0) { skl[warp] = akl; sce[warp] = ace; }
    __syncthreads();
    if (tid == 0) {
        float k = 0.f, c2 = 0.f;
#pragma unroll
        for (int w = 0; w < 8; ++w) { k += skl[w]; c2 += sce[w]; }
        out[0] = BETA_C * (k / (float)B_ROWS) + ALPHA_C * (c2 / (float)B_ROWS);
    }
}

// ---------------------------------------------------------------------------
extern "C" void kernel_launch(void* const* d_in, const int* in_sizes, int n_in,
                              void* d_out, int out_size) {
    const float* emb    = (const float*)d_in[0];
    const float* scores = (const float*)d_in[1];

    cudaFuncSetAttribute(gemm_z_kernel,
                         cudaFuncAttributeMaxDynamicSharedMemorySize, GEMM_SMEM_TOTAL);

    prep_kernel<<<B_ROWS, 320>>>(emb, scores);
    dim3 grid(NTGT / TILE_N, B_ROWS / TILE_M);   // (144, 32)
    gemm_z_kernel<<<grid, 256, GEMM_SMEM_TOTAL>>>();
    finalize_kernel<<<1, 256>>>((float*)d_out);
}